// round 1
// baseline (speedup 1.0000x reference)
#include <cuda_runtime.h>

// BQNN_hardware: 14 Givens rotations on a 6x6 complex unitary, tracking only
// columns 0 and 3; 15 pair amplitudes, L2-normalized, abs out.

#define TPB 256

static __device__ __forceinline__ void rot6(
    float (&ur)[6], float (&ui)[6], int i, int j,
    float ar, float ai, float cr, float ci, float ct, float st)
{
    float pir = ur[i], pii = ui[i];
    float pjr = ur[j], pji = ui[j];
    ur[i] = ar * pir - ai * pii - st * pjr;
    ui[i] = ar * pii + ai * pir - st * pji;
    ur[j] = cr * pir - ci * pii + ct * pjr;
    ui[j] = cr * pii + ci * pir + ct * pji;
}

__global__ __launch_bounds__(TPB)
void bqnn_kernel(const float* __restrict__ x,
                 const float* __restrict__ pphi,
                 const float* __restrict__ pth,
                 const float* __restrict__ ink,
                 const float* __restrict__ inb,
                 float* __restrict__ out,
                 int batch)
{
    __shared__ float sout[TPB * 15];
    const int t   = threadIdx.x;
    const int row = blockIdx.x * TPB + t;
    const bool valid = row < batch;

    // ---- load x row (48B aligned -> 3x float4) and apply k/b scaling ----
    float xs[12];
    {
        float4 k0 = __ldg((const float4*)(ink + 0));
        float4 k1 = __ldg((const float4*)(ink + 4));
        float4 k2 = __ldg((const float4*)(ink + 8));
        float4 b0 = __ldg((const float4*)(inb + 0));
        float4 b1 = __ldg((const float4*)(inb + 4));
        float4 b2 = __ldg((const float4*)(inb + 8));
        float4 x0 = make_float4(0.f, 0.f, 0.f, 0.f), x1 = x0, x2 = x0;
        if (valid) {
            const float4* xp = (const float4*)(x + (size_t)row * 12);
            x0 = xp[0]; x1 = xp[1]; x2 = xp[2];
        }
        xs[0]  = fmaf(x0.x, k0.x, b0.x);
        xs[1]  = fmaf(x0.y, k0.y, b0.y);
        xs[2]  = fmaf(x0.z, k0.z, b0.z);
        xs[3]  = fmaf(x0.w, k0.w, b0.w);
        xs[4]  = fmaf(x1.x, k1.x, b1.x);
        xs[5]  = fmaf(x1.y, k1.y, b1.y);
        xs[6]  = fmaf(x1.z, k1.z, b1.z);
        xs[7]  = fmaf(x1.w, k1.w, b1.w);
        xs[8]  = fmaf(x2.x, k2.x, b2.x);
        xs[9]  = fmaf(x2.y, k2.y, b2.y);
        xs[10] = fmaf(x2.z, k2.z, b2.z);
        xs[11] = fmaf(x2.w, k2.w, b2.w);
    }

    // ---- per-mode sincos ----
    // theta: k0-3=pth[0..3], k4-6=xs[3..5], k7-8=pth[4..5], k9-11=xs[9..11], k12-13=pth[6..7]
    // phi:   k0-3=0,         k4-6=xs[0..2], k7-8=pphi[0..1], k9-11=xs[6..8], k12-13=pphi[2..3]
    float ct[14], st[14], cp[14], sp[14];
    {
#pragma unroll
        for (int k = 0; k < 4; k++) {
            __sincosf(__ldg(pth + k), &st[k], &ct[k]);
            cp[k] = 1.0f; sp[k] = 0.0f;
        }
        __sincosf(__ldg(pth + 4), &st[7],  &ct[7]);
        __sincosf(__ldg(pphi + 0), &sp[7],  &cp[7]);
        __sincosf(__ldg(pth + 5), &st[8],  &ct[8]);
        __sincosf(__ldg(pphi + 1), &sp[8],  &cp[8]);
        __sincosf(__ldg(pth + 6), &st[12], &ct[12]);
        __sincosf(__ldg(pphi + 2), &sp[12], &cp[12]);
        __sincosf(__ldg(pth + 7), &st[13], &ct[13]);
        __sincosf(__ldg(pphi + 3), &sp[13], &cp[13]);
#pragma unroll
        for (int m = 0; m < 3; m++) {
            __sincosf(xs[3 + m], &st[4 + m], &ct[4 + m]);
            __sincosf(xs[m],     &sp[4 + m], &cp[4 + m]);
            __sincosf(xs[9 + m], &st[9 + m], &ct[9 + m]);
            __sincosf(xs[6 + m], &sp[9 + m], &cp[9 + m]);
        }
    }

    // ---- propagate columns 0 and 3 through 14 rotations ----
    float c0r[6] = {1.f, 0.f, 0.f, 0.f, 0.f, 0.f};
    float c0i[6] = {0.f, 0.f, 0.f, 0.f, 0.f, 0.f};
    float c3r[6] = {0.f, 0.f, 0.f, 1.f, 0.f, 0.f};
    float c3i[6] = {0.f, 0.f, 0.f, 0.f, 0.f, 0.f};

    const int MI[14] = {0, 4, 1, 3, 0, 2, 4, 1, 3, 0, 2, 4, 1, 3};
    const int MJ[14] = {1, 5, 2, 4, 1, 3, 5, 2, 4, 1, 3, 5, 2, 4};
#pragma unroll
    for (int k = 0; k < 14; k++) {
        const int i = MI[k], j = MJ[k];
        float ar = cp[k] * ct[k], ai = sp[k] * ct[k];
        float cr = cp[k] * st[k], ci = sp[k] * st[k];
        rot6(c0r, c0i, i, j, ar, ai, cr, ci, ct[k], st[k]);
        rot6(c3r, c3i, i, j, ar, ai, cr, ci, ct[k], st[k]);
    }

    // ---- 15 pair amplitudes: amp = col0[i]*col3[j] + col3[i]*col0[j] ----
    const int PA[15] = {0, 0, 0, 0, 0, 1, 1, 1, 1, 2, 2, 2, 3, 3, 4};
    const int PB[15] = {1, 2, 3, 4, 5, 2, 3, 4, 5, 3, 4, 5, 4, 5, 5};
    float mag2[15];
    float sum = 0.f;
#pragma unroll
    for (int p = 0; p < 15; p++) {
        const int i = PA[p], j = PB[p];
        float re = c0r[i] * c3r[j] - c0i[i] * c3i[j]
                 + c3r[i] * c0r[j] - c3i[i] * c0i[j];
        float im = c0r[i] * c3i[j] + c0i[i] * c3r[j]
                 + c3r[i] * c0i[j] + c3i[i] * c0r[j];
        mag2[p] = re * re + im * im;
        sum += mag2[p];
    }
    float nrm = sqrtf(sum);
    float rn  = 1.0f / fmaxf(nrm, 1e-12f);
#pragma unroll
    for (int p = 0; p < 15; p++)
        sout[t * 15 + p] = sqrtf(mag2[p]) * rn;

    __syncthreads();

    // ---- coalesced write of the block's output tile ----
    const int base = blockIdx.x * TPB;
    const int rows = min(TPB, batch - base);
    float* gout = out + (size_t)base * 15;
    if (rows == TPB) {
        float4* g4 = (float4*)gout;
        const float4* s4 = (const float4*)sout;
#pragma unroll
        for (int i = 0; i < 4; i++) {
            int idx = t + i * TPB;
            if (idx < (TPB * 15) / 4) g4[idx] = s4[idx];
        }
    } else if (rows > 0) {
        for (int idx = t; idx < rows * 15; idx += TPB) gout[idx] = sout[idx];
    }
}

extern "C" void kernel_launch(void* const* d_in, const int* in_sizes, int n_in,
                              void* d_out, int out_size)
{
    const float* x    = (const float*)d_in[0];
    const float* pphi = (const float*)d_in[1];
    const float* pth  = (const float*)d_in[2];
    const float* ink  = (const float*)d_in[3];
    const float* inb  = (const float*)d_in[4];
    float* out = (float*)d_out;

    int batch = in_sizes[0] / 12;
    int grid  = (batch + TPB - 1) / TPB;
    bqnn_kernel<<<grid, TPB>>>(x, pphi, pth, ink, inb, out, batch);
}